// round 15
// baseline (speedup 1.0000x reference)
#include <cuda_runtime.h>
#include <cuda_bf16.h>
#include <cmath>

#define B_   256
#define U_   512
#define D_   16
#define M_   256

// device globals (allocation-free rule)
__device__ float g_hp[4][B_ * 1024];
__device__ __nv_bfloat16 g_hh[B_ * 1024];
__device__ __nv_bfloat16 g_hl[B_ * 1024];
__device__ __nv_bfloat16 g_w2h[8192 * 1024];
__device__ __nv_bfloat16 g_w2l[8192 * 1024];
__device__ __nv_bfloat16 g_ah[B_ * 8192];
__device__ __nv_bfloat16 g_al[B_ * 8192];
__device__ __nv_bfloat16 g_mah[U_ * M_ * D_];
__device__ __nv_bfloat16 g_mal[U_ * M_ * D_];
__device__ __nv_bfloat16 g_mvth[U_ * D_ * M_];
__device__ __nv_bfloat16 g_mvtl[U_ * D_ * M_];

typedef unsigned long long ull;
union F4U { float4 f; ull p[2]; float s[4]; };

__device__ __forceinline__ ull pk2(float a, float b) {
    ull r; asm("mov.b64 %0, {%1, %2};" : "=l"(r) : "f"(a), "f"(b)); return r;
}
__device__ __forceinline__ void upk2(ull v, float& a, float& b) {
    asm("mov.b64 {%0, %1}, %2;" : "=f"(a), "=f"(b) : "l"(v));
}
__device__ __forceinline__ void ffma2(ull& d, ull a, ull b) {
    asm("fma.rn.f32x2 %0, %1, %2, %0;" : "+l"(d) : "l"(a), "l"(b));
}
__device__ __forceinline__ void ldsm4(unsigned* r, unsigned addr) {
    asm volatile("ldmatrix.sync.aligned.m8n8.x4.shared.b16 {%0,%1,%2,%3}, [%4];"
        : "=r"(r[0]), "=r"(r[1]), "=r"(r[2]), "=r"(r[3]) : "r"(addr));
}
__device__ __forceinline__ void ldsm2(unsigned* r, unsigned addr) {
    asm volatile("ldmatrix.sync.aligned.m8n8.x2.shared.b16 {%0,%1}, [%2];"
        : "=r"(r[0]), "=r"(r[1]) : "r"(addr));
}
__device__ __forceinline__ void mma16816(float* d, const unsigned* a, const unsigned* b) {
    asm volatile(
        "mma.sync.aligned.m16n8k16.row.col.f32.bf16.bf16.f32 "
        "{%0,%1,%2,%3}, {%4,%5,%6,%7}, {%8,%9}, {%0,%1,%2,%3};"
        : "+f"(d[0]), "+f"(d[1]), "+f"(d[2]), "+f"(d[3])
        : "r"(a[0]), "r"(a[1]), "r"(a[2]), "r"(a[3]), "r"(b[0]), "r"(b[1]));
}
__device__ __forceinline__ unsigned pkbf2(float a, float b) {
    __nv_bfloat162 t = __floats2bfloat162_rn(a, b);
    return *(unsigned*)&t;
}
__device__ __forceinline__ void cpa16(unsigned dst, const void* src) {
    asm volatile("cp.async.cg.shared.global [%0], [%1], 16;" :: "r"(dst), "l"(src));
}

// ---------------------------------------------------------------------------
// GEMM1 partials (unchanged, passing)
// ---------------------------------------------------------------------------
__global__ void __launch_bounds__(128) gemm1_partial(
        const float* __restrict__ A, const float* __restrict__ Bm)
{
    __shared__ float As[16][68];
    __shared__ float Bs[16][32];

    const int tid = threadIdx.x;
    const int bx = blockIdx.x, by = blockIdx.y, bz = blockIdx.z;
    const int kBegin = bz * 256;
    const int tx = tid & 7;
    const int ty = tid >> 3;

    ull acc2[2][4];
    acc2[0][0]=0ull; acc2[0][1]=0ull; acc2[0][2]=0ull; acc2[0][3]=0ull;
    acc2[1][0]=0ull; acc2[1][1]=0ull; acc2[1][2]=0ull; acc2[1][3]=0ull;

    const float* Ablk = A + (size_t)by * 64 * 1024;
    const float* Bblk = Bm + bx * 32;

    const int ar = tid >> 2;
    const int akq = tid & 3;
    const int bkr = tid >> 3;
    const int bnq = tid & 7;

    {
        float4 v0 = *(const float4*)(Ablk + (size_t)ar * 1024 + kBegin + akq * 4);
        As[akq*4+0][ar] = v0.x; As[akq*4+1][ar] = v0.y;
        As[akq*4+2][ar] = v0.z; As[akq*4+3][ar] = v0.w;
        float4 v1 = *(const float4*)(Ablk + (size_t)(ar+32) * 1024 + kBegin + akq * 4);
        As[akq*4+0][ar+32] = v1.x; As[akq*4+1][ar+32] = v1.y;
        As[akq*4+2][ar+32] = v1.z; As[akq*4+3][ar+32] = v1.w;
        float4 vb = *(const float4*)(Bblk + (size_t)(kBegin + bkr) * 1024 + bnq * 4);
        *(float4*)(&Bs[bkr][bnq*4]) = vb;
    }
    __syncthreads();

    for (int k0 = kBegin; k0 < kBegin + 256; k0 += 16) {
        const bool more = (k0 + 16) < (kBegin + 256);
        float4 nA0, nA1, nB0;
        if (more) {
            nA0 = *(const float4*)(Ablk + (size_t)ar * 1024 + k0 + 16 + akq * 4);
            nA1 = *(const float4*)(Ablk + (size_t)(ar+32) * 1024 + k0 + 16 + akq * 4);
            nB0 = *(const float4*)(Bblk + (size_t)(k0 + 16 + bkr) * 1024 + bnq * 4);
        }
#pragma unroll
        for (int k = 0; k < 16; k++) {
            F4U ta; ta.f = *(const float4*)(&As[k][ty*4]);
            float4 vb = *(const float4*)(&Bs[k][tx*4]);
            ull bd0 = pk2(vb.x, vb.x);
            ull bd1 = pk2(vb.y, vb.y);
            ull bd2 = pk2(vb.z, vb.z);
            ull bd3 = pk2(vb.w, vb.w);
            ffma2(acc2[0][0], ta.p[0], bd0);
            ffma2(acc2[0][1], ta.p[0], bd1);
            ffma2(acc2[0][2], ta.p[0], bd2);
            ffma2(acc2[0][3], ta.p[0], bd3);
            ffma2(acc2[1][0], ta.p[1], bd0);
            ffma2(acc2[1][1], ta.p[1], bd1);
            ffma2(acc2[1][2], ta.p[1], bd2);
            ffma2(acc2[1][3], ta.p[1], bd3);
        }
        if (more) {
            __syncthreads();
            As[akq*4+0][ar] = nA0.x; As[akq*4+1][ar] = nA0.y;
            As[akq*4+2][ar] = nA0.z; As[akq*4+3][ar] = nA0.w;
            As[akq*4+0][ar+32] = nA1.x; As[akq*4+1][ar+32] = nA1.y;
            As[akq*4+2][ar+32] = nA1.z; As[akq*4+3][ar+32] = nA1.w;
            *(float4*)(&Bs[bkr][bnq*4]) = nB0;
            __syncthreads();
        }
    }

    float* Cs = &g_hp[bz][0];
#pragma unroll
    for (int r2 = 0; r2 < 2; r2++) {
        float s0[4], s1[4];
        upk2(acc2[r2][0], s0[0], s1[0]);
        upk2(acc2[r2][1], s0[1], s1[1]);
        upk2(acc2[r2][2], s0[2], s1[2]);
        upk2(acc2[r2][3], s0[3], s1[3]);
        int row0 = by*64 + ty*4 + 2*r2;
        int col = bx*32 + tx*4;
        *(float4*)(Cs + (size_t)row0 * 1024 + col) =
            make_float4(s0[0], s0[1], s0[2], s0[3]);
        *(float4*)(Cs + (size_t)(row0 + 1) * 1024 + col) =
            make_float4(s1[0], s1[1], s1[2], s1[3]);
    }
}

// ---------------------------------------------------------------------------
__global__ void __launch_bounds__(256) reduce_bias_h(const float* __restrict__ bias)
{
    int i = blockIdx.x * 256 + threadIdx.x;
    int col4 = i & 255;
    float4 a = *(const float4*)(&g_hp[0][i*4]);
    float4 b = *(const float4*)(&g_hp[1][i*4]);
    float4 c = *(const float4*)(&g_hp[2][i*4]);
    float4 d = *(const float4*)(&g_hp[3][i*4]);
    float4 bb = *(const float4*)(bias + col4*4);
    float v0 = a.x + b.x + c.x + d.x + bb.x;
    float v1 = a.y + b.y + c.y + d.y + bb.y;
    float v2 = a.z + b.z + c.z + d.z + bb.z;
    float v3 = a.w + b.w + c.w + d.w + bb.w;

    unsigned h01 = pkbf2(v0, v1);
    unsigned h23 = pkbf2(v2, v3);
    __nv_bfloat162 hh01 = *(__nv_bfloat162*)&h01;
    __nv_bfloat162 hh23 = *(__nv_bfloat162*)&h23;
    unsigned l01 = pkbf2(v0 - __low2float(hh01), v1 - __high2float(hh01));
    unsigned l23 = pkbf2(v2 - __low2float(hh23), v3 - __high2float(hh23));
    *(uint2*)(&g_hh[i*4]) = make_uint2(h01, h23);
    *(uint2*)(&g_hl[i*4]) = make_uint2(l01, l23);
}

// ---------------------------------------------------------------------------
__global__ void __launch_bounds__(256) w2conv_k(const float* __restrict__ W2)
{
    __shared__ float t[32][33];
    const int n0 = blockIdx.x * 32;
    const int k0 = blockIdx.y * 32;
    const int tid = threadIdx.x;
#pragma unroll
    for (int i = 0; i < 4; i++) {
        int idx = tid + i * 256;
        int kr = idx >> 5;
        int nc = idx & 31;
        t[kr][nc] = W2[(size_t)(k0 + kr) * 8192 + n0 + nc];
    }
    __syncthreads();
    int n = tid >> 3;
    int kc = tid & 7;
    float v0 = t[kc*4+0][n], v1 = t[kc*4+1][n], v2 = t[kc*4+2][n], v3 = t[kc*4+3][n];
    unsigned h01 = pkbf2(v0, v1);
    unsigned h23 = pkbf2(v2, v3);
    __nv_bfloat162 hh01 = *(__nv_bfloat162*)&h01;
    __nv_bfloat162 hh23 = *(__nv_bfloat162*)&h23;
    unsigned l01 = pkbf2(v0 - __low2float(hh01), v1 - __high2float(hh01));
    unsigned l23 = pkbf2(v2 - __low2float(hh23), v3 - __high2float(hh23));
    size_t o = (size_t)(n0 + n) * 1024 + k0 + kc*4;
    *(uint2*)(&g_w2h[o]) = make_uint2(h01, h23);
    *(uint2*)(&g_w2l[o]) = make_uint2(l01, l23);
}

// ---------------------------------------------------------------------------
__global__ void __launch_bounds__(256) mvconv_k(
        const float* __restrict__ Ma, const float* __restrict__ Mv)
{
    __shared__ float tv[16][68];
    const int u  = blockIdx.x;
    const int m0 = blockIdx.y * 64;
    const int t  = threadIdx.x;
    const int ml = t >> 2;
    const int q  = t & 3;

    {
        float4 v = *(const float4*)(Ma + ((size_t)(m0+ml)*512 + u)*16 + q*4);
        unsigned h01 = pkbf2(v.x, v.y);
        unsigned h23 = pkbf2(v.z, v.w);
        __nv_bfloat162 hh01 = *(__nv_bfloat162*)&h01;
        __nv_bfloat162 hh23 = *(__nv_bfloat162*)&h23;
        unsigned l01 = pkbf2(v.x - __low2float(hh01), v.y - __high2float(hh01));
        unsigned l23 = pkbf2(v.z - __low2float(hh23), v.w - __high2float(hh23));
        size_t o = ((size_t)u*256 + m0 + ml)*16 + q*4;
        *(uint2*)(&g_mah[o]) = make_uint2(h01, h23);
        *(uint2*)(&g_mal[o]) = make_uint2(l01, l23);
    }
    {
        float4 v = *(const float4*)(Mv + ((size_t)(m0+ml)*512 + u)*16 + q*4);
        tv[q*4+0][ml] = v.x;
        tv[q*4+1][ml] = v.y;
        tv[q*4+2][ml] = v.z;
        tv[q*4+3][ml] = v.w;
    }
    __syncthreads();
    {
        int d = t >> 4;
        int mq = t & 15;
        float v0 = tv[d][mq*4+0], v1 = tv[d][mq*4+1];
        float v2 = tv[d][mq*4+2], v3 = tv[d][mq*4+3];
        unsigned h01 = pkbf2(v0, v1);
        unsigned h23 = pkbf2(v2, v3);
        __nv_bfloat162 hh01 = *(__nv_bfloat162*)&h01;
        __nv_bfloat162 hh23 = *(__nv_bfloat162*)&h23;
        unsigned l01 = pkbf2(v0 - __low2float(hh01), v1 - __high2float(hh01));
        unsigned l23 = pkbf2(v2 - __low2float(hh23), v3 - __high2float(hh23));
        size_t o = ((size_t)u*16 + d)*256 + m0 + mq*4;
        *(uint2*)(&g_mvth[o]) = make_uint2(h01, h23);
        *(uint2*)(&g_mvtl[o]) = make_uint2(l01, l23);
    }
}

// ---------------------------------------------------------------------------
// GEMM2 v2: HMMA bf16 split-2 with 3-stage cp.async pipeline + B ldsm4 merge.
// Buffer layout (bytes, per 30720B stage): A_H 0, A_L 10240, B_H 20480, B_L 25600.
// ---------------------------------------------------------------------------
__global__ void __launch_bounds__(256) hgemm2_k(
        const float* __restrict__ bias, float* __restrict__ C)
{
    extern __shared__ __align__(16) char hsm[];
    const unsigned sbase = (unsigned)__cvta_generic_to_shared(hsm);
    const int tid = threadIdx.x;
    const int lane = tid & 31;
    const int wid = tid >> 5;
    const int wm = wid & 3;
    const int wn = wid >> 2;
    const int n0 = blockIdx.x * 64;
    const int m0 = blockIdx.y * 128;

    const int ar0 = tid >> 2;
    const int akq = tid & 3;
    const int ar1 = ar0 + 64;
    const unsigned dA0 = (unsigned)(ar0*40 + akq*8) * 2u;
    const unsigned dA1 = (unsigned)(ar1*40 + akq*8) * 2u;
    const unsigned dB  = dA0;

    unsigned aOffH[2];
#pragma unroll
    for (int ti = 0; ti < 2; ti++) {
        int row = wm*32 + ti*16 + (lane & 15);
        int kb  = (lane >> 4) * 8;
        aOffH[ti] = (unsigned)(row*40 + kb) * 2u;
    }
    unsigned bOff4[2];
#pragma unroll
    for (int tjp = 0; tjp < 2; tjp++) {
        int row = wn*32 + tjp*16 + (lane & 7) + ((lane >> 4) & 1) * 8;
        int kb  = ((lane >> 3) & 1) * 8;
        bOff4[tjp] = 20480u + (unsigned)(row*40 + kb) * 2u;
    }

    float acc[2][4][4];
#pragma unroll
    for (int ti = 0; ti < 2; ti++)
#pragma unroll
        for (int tj = 0; tj < 4; tj++) {
            acc[ti][tj][0] = 0.f; acc[ti][tj][1] = 0.f;
            acc[ti][tj][2] = 0.f; acc[ti][tj][3] = 0.f;
        }

    const size_t sa0 = (size_t)(m0 + ar0) * 1024 + akq*8;
    const size_t sa1 = (size_t)(m0 + ar1) * 1024 + akq*8;
    const size_t sb  = (size_t)(n0 + ar0) * 1024 + akq*8;

    // prologue: issue stages 0 and 1
#pragma unroll
    for (int pf = 0; pf < 2; pf++) {
        unsigned buf = sbase + (unsigned)pf * 30720u;
        int kk = pf * 32;
        cpa16(buf + dA0,          &g_hh[sa0 + kk]);
        cpa16(buf + dA1,          &g_hh[sa1 + kk]);
        cpa16(buf + 10240u + dA0, &g_hl[sa0 + kk]);
        cpa16(buf + 10240u + dA1, &g_hl[sa1 + kk]);
        cpa16(buf + 20480u + dB,  &g_w2h[sb + kk]);
        cpa16(buf + 25600u + dB,  &g_w2l[sb + kk]);
        asm volatile("cp.async.commit_group;" ::: "memory");
    }

    for (int it = 0; it < 32; ++it) {
        if (it < 31)
            asm volatile("cp.async.wait_group 1;" ::: "memory");
        else
            asm volatile("cp.async.wait_group 0;" ::: "memory");
        __syncthreads();

        if (it + 2 < 32) {
            unsigned buf = sbase + (unsigned)((it + 2) % 3) * 30720u;
            int kk = (it + 2) * 32;
            cpa16(buf + dA0,          &g_hh[sa0 + kk]);
            cpa16(buf + dA1,          &g_hh[sa1 + kk]);
            cpa16(buf + 10240u + dA0, &g_hl[sa0 + kk]);
            cpa16(buf + 10240u + dA1, &g_hl[sa1 + kk]);
            cpa16(buf + 20480u + dB,  &g_w2h[sb + kk]);
            cpa16(buf + 25600u + dB,  &g_w2l[sb + kk]);
            asm volatile("cp.async.commit_group;" ::: "memory");
        }

        const unsigned base = sbase + (unsigned)(it % 3) * 30720u;
#pragma unroll
        for (int ks = 0; ks < 2; ks++) {
            const unsigned ko = (unsigned)ks * 32u;
            unsigned fah[2][4], fal[2][4], fbh[2][4], fbl[2][4];
#pragma unroll
            for (int ti = 0; ti < 2; ti++) {
                ldsm4(fah[ti], base + aOffH[ti] + ko);
                ldsm4(fal[ti], base + aOffH[ti] + 10240u + ko);
            }
#pragma unroll
            for (int tjp = 0; tjp < 2; tjp++) {
                ldsm4(fbh[tjp], base + bOff4[tjp] + ko);
                ldsm4(fbl[tjp], base + bOff4[tjp] + 5120u + ko);
            }
#pragma unroll
            for (int ti = 0; ti < 2; ti++)
#pragma unroll
                for (int tj = 0; tj < 4; tj++) {
                    const unsigned* bh = &fbh[tj >> 1][(tj & 1) * 2];
                    const unsigned* bl = &fbl[tj >> 1][(tj & 1) * 2];
                    mma16816(acc[ti][tj], fah[ti], bh);
                    mma16816(acc[ti][tj], fah[ti], bl);
                    mma16816(acc[ti][tj], fal[ti], bh);
                }
        }
    }

    const int gq = lane >> 2;
    const int t2 = (lane & 3) * 2;
#pragma unroll
    for (int ti = 0; ti < 2; ti++) {
        int row = m0 + wm*32 + ti*16 + gq;
#pragma unroll
        for (int tj = 0; tj < 4; tj++) {
            int col = n0 + wn*32 + tj*8 + t2;
            float2 bb = *(const float2*)(bias + col);
            float v0 = acc[ti][tj][0] + bb.x;
            float v1 = acc[ti][tj][1] + bb.y;
            float v2 = acc[ti][tj][2] + bb.x;
            float v3 = acc[ti][tj][3] + bb.y;
            *(float2*)(C + (size_t)row * 8192 + col) = make_float2(v0, v1);
            *(float2*)(C + (size_t)(row + 8) * 8192 + col) = make_float2(v2, v3);
            unsigned h01 = pkbf2(v0, v1);
            __nv_bfloat162 hh01 = *(__nv_bfloat162*)&h01;
            unsigned l01 = pkbf2(v0 - __low2float(hh01), v1 - __high2float(hh01));
            *(unsigned*)(&g_ah[(size_t)row*8192 + col]) = h01;
            *(unsigned*)(&g_al[(size_t)row*8192 + col]) = l01;
            unsigned h23 = pkbf2(v2, v3);
            __nv_bfloat162 hh23 = *(__nv_bfloat162*)&h23;
            unsigned l23 = pkbf2(v2 - __low2float(hh23), v3 - __high2float(hh23));
            *(unsigned*)(&g_ah[(size_t)(row+8)*8192 + col]) = h23;
            *(unsigned*)(&g_al[(size_t)(row+8)*8192 + col]) = l23;
        }
    }
}

// ---------------------------------------------------------------------------
// Fused v8.1: PERSISTENT-U, 512 threads, double-buffered sA prefetch.
// smem bytes: sS   fp32 [4u*16b][264]     [0,      67584)
//             sA   2 bufs [u][16b][80]    [67584,  77824)
//             sMa  [u][256m][80]          [77824,  159744)
//             sMvT [u][16d][1040]         [159744, 226304)
//             sRed [8 slots][512]         [226304, 230400)
// ---------------------------------------------------------------------------
__global__ void __launch_bounds__(512) fused_attn(
        const float* __restrict__ temp,
        float* __restrict__ wout,
        float* __restrict__ outp)
{
    extern __shared__ __align__(16) char smc[];
    float* sS = (float*)smc;
    const unsigned sbase = (unsigned)__cvta_generic_to_shared(smc);

    const int u0  = blockIdx.x * 4;
    const int tid = threadIdx.x;
    const int lane = tid & 31;
    const int wid  = tid >> 5;       // 0..15
    const int p    = wid >> 2;       // local u 0..3
    const int q    = wid & 3;        // quarter index
    const int ug   = u0 + p;

    const float tu = temp[ug];

    // ---- resident loads: Ma planes -> sMa, MvT planes -> sMvT ----
#pragma unroll
    for (int t = 0; t < 4; t++) {
        int idx = tid + t*512;            // 0..2047
        int ul = idx >> 9;
        int m  = (idx >> 1) & 255;
        int hf = idx & 1;
        size_t gi = (((size_t)(u0 + ul)*256 + m)*16) + hf*8;
        uint4 vh = *(const uint4*)(&g_mah[gi]);
        uint4 vl = *(const uint4*)(&g_mal[gi]);
        char* d = smc + 77824 + ul*20480 + m*80 + hf*16;
        *(uint4*)d = vh;
        *(uint4*)(d + 32) = vl;
    }
#pragma unroll
    for (int t = 0; t < 4; t++) {
        int idx = tid + t*512;
        int ul  = idx >> 9;
        int dd  = (idx >> 5) & 15;
        int seg = idx & 31;
        size_t gi = (((size_t)(u0 + ul)*16 + dd)*256) + seg*8;
        uint4 vh = *(const uint4*)(&g_mvth[gi]);
        uint4 vl = *(const uint4*)(&g_mvtl[gi]);
        char* pp = smc + 159744 + ul*16640 + dd*1040 + seg*16;
        *(uint4*)pp = vh;
        *(uint4*)(pp + 512) = vl;
    }

    // ---- prologue: stage attn tile for it=0 into sA buf0 ----
    {
        int b = lane >> 1, hf = lane & 1;
        size_t gi = (size_t)b * 8192 + (size_t)ug * 16 + hf * 8;   // b0 = 0
        uint4 vh = *(const uint4*)(&g_ah[gi]);
        uint4 vl = *(const uint4*)(&g_al[gi]);
        char* pa = smc + 67584 + p*1280 + b*80 + hf*16;
        *(uint4*)pa = vh;
        *(uint4*)(pa + 32) = vl;
    }
    __syncthreads();

    const unsigned sMa_u = sbase + 77824u  + (unsigned)p * 20480u;
    const unsigned sMv_u = sbase + 159744u + (unsigned)p * 16640u;
    char* cRed = smc + 226304;

    for (int it = 0; it < 16; it++) {
        const int b0 = it * 16;

        // ---- stage 0: ldsm attn fragments from current buffer ----
        unsigned fa_h[4], fa_l[4];
        {
            unsigned a = sbase + 67584u + (unsigned)((it & 1) * 5120 + p * 1280)
                       + (unsigned)((lane & 15) * 80 + (lane >> 4) * 16);
            ldsm4(fa_h, a);
            ldsm4(fa_l, a + 32u);
        }
        // prefetch next attn tile into registers
        uint4 nvh, nvl;
        const bool more = (it < 15);
        if (more) {
            int b = lane >> 1, hf = lane & 1;
            size_t gi = (size_t)(b0 + 16 + b) * 8192 + (size_t)ug * 16 + hf * 8;
            nvh = *(const uint4*)(&g_ah[gi]);
            nvl = *(const uint4*)(&g_al[gi]);
        }

        // ---- stage 1: scores; this warp: m in [q*64, q*64+64) ----
        {
            const int gq = lane >> 2, t2 = (lane & 3) * 2;
#pragma unroll 4
            for (int tj = 0; tj < 8; tj++) {
                int mbase = q*64 + tj*8;
                unsigned fb_h[2], fb_l[2];
                unsigned ba = sMa_u + (unsigned)((mbase + (lane & 7))*80 + ((lane >> 3) & 1)*16);
                ldsm2(fb_h, ba);
                ldsm2(fb_l, ba + 32u);
                float d4[4];
                d4[0] = 0.f; d4[1] = 0.f; d4[2] = 0.f; d4[3] = 0.f;
                mma16816(d4, fa_h, fb_h);
                mma16816(d4, fa_h, fb_l);
                mma16816(d4, fa_l, fb_h);
                int m = mbase + t2;
                float s0 = (m     == b0 + gq)     ? -INFINITY : d4[0] * tu;
                float s1 = (m + 1 == b0 + gq)     ? -INFINITY : d4[1] * tu;
                float s2 = (m     == b0 + gq + 8) ? -INFINITY : d4[2] * tu;
                float s3 = (m + 1 == b0 + gq + 8) ? -INFINITY : d4[3] * tu;
                *(float2*)(sS + (p*16 + gq)*264 + m)     = make_float2(s0, s1);
                *(float2*)(sS + (p*16 + gq + 8)*264 + m) = make_float2(s2, s3);
            }
        }
        // u-group barrier (128 threads of this u): all m-quarters done
        asm volatile("bar.sync %0, %1;" :: "r"(p + 1), "r"(128) : "memory");

        // ---- stage 2: grouped softmax; one group per lane ----
        {
            int g = lane & 7;
            int b = q*4 + (lane >> 3);
            float* row = sS + (p*16 + b)*264 + g;
            float v[32];
            float mx = -INFINITY;
#pragma unroll
            for (int j = 0; j < 32; j++) { v[j] = row[j*8]; mx = fmaxf(mx, v[j]); }
            float s = 0.f;
#pragma unroll
            for (int j = 0; j < 32; j++) { v[j] = __expf(v[j] - mx); s += v[j]; }
            float inv = 1.f / (8.f * s);
#pragma unroll
            for (int j = 0; j < 32; j++) row[j*8] = v[j] * inv;
        }
        __syncthreads();

        // ---- stage 2b: weights store [b][m][u0..u0+3] (16B stores) ----
        {
            int b = tid >> 5;              // 0..15
#pragma unroll
            for (int mj = 0; mj < 8; mj++) {
                int m = lane + 32*mj;
                float4 w;
                w.x = sS[(0*16 + b)*264 + m];
                w.y = sS[(1*16 + b)*264 + m];
                w.z = sS[(2*16 + b)*264 + m];
                w.w = sS[(3*16 + b)*264 + m];
                *(float4*)(wout + ((size_t)(b0 + b)*256 + m)*512 + u0) = w;
            }
        }

        // ---- stage 3: outputs; warp = (d-half dh, mc-half mh) ----
        {
            const int dh = q & 1;
            const int mh = q >> 1;
            float aA[4], aB[4], aC[4];
            aA[0]=0.f; aA[1]=0.f; aA[2]=0.f; aA[3]=0.f;
            aB[0]=0.f; aB[1]=0.f; aB[2]=0.f; aB[3]=0.f;
            aC[0]=0.f; aC[1]=0.f; aC[2]=0.f; aC[3]=0.f;
            const int gr = lane >> 2;
            const int kc = (lane & 3) * 2;
#pragma unroll 4
            for (int mi = 0; mi < 8; mi++) {
                int mc = mh*8 + mi;
                const float* r0 = sS + (p*16 + gr)*264 + mc*16;
                const float* r1 = sS + (p*16 + gr + 8)*264 + mc*16;
                float2 v00 = *(const float2*)(r0 + kc);
                float2 v10 = *(const float2*)(r1 + kc);
                float2 v01 = *(const float2*)(r0 + kc + 8);
                float2 v11 = *(const float2*)(r1 + kc + 8);
                unsigned a_h[4], a_l[4];
                a_h[0] = pkbf2(v00.x, v00.y);
                a_h[1] = pkbf2(v10.x, v10.y);
                a_h[2] = pkbf2(v01.x, v01.y);
                a_h[3] = pkbf2(v11.x, v11.y);
                __nv_bfloat162 t0 = *(__nv_bfloat162*)&a_h[0];
                __nv_bfloat162 t1 = *(__nv_bfloat162*)&a_h[1];
                __nv_bfloat162 t2b = *(__nv_bfloat162*)&a_h[2];
                __nv_bfloat162 t3 = *(__nv_bfloat162*)&a_h[3];
                a_l[0] = pkbf2(v00.x - __low2float(t0), v00.y - __high2float(t0));
                a_l[1] = pkbf2(v10.x - __low2float(t1), v10.y - __high2float(t1));
                a_l[2] = pkbf2(v01.x - __low2float(t2b), v01.y - __high2float(t2b));
                a_l[3] = pkbf2(v11.x - __low2float(t3), v11.y - __high2float(t3));
                unsigned fb_h[2], fb_l[2];
                unsigned ba = sMv_u + (unsigned)((dh*8 + (lane & 7))*1040 + mc*32 + ((lane >> 3) & 1)*16);
                ldsm2(fb_h, ba);
                ldsm2(fb_l, ba + 512u);
                mma16816(aA, a_h, fb_h);
                mma16816(aB, a_h, fb_l);
                mma16816(aC, a_l, fb_h);
            }
            float c0 = aA[0] + aB[0] + aC[0];
            float c1 = aA[1] + aB[1] + aC[1];
            float c2 = aA[2] + aB[2] + aC[2];
            float c3 = aA[3] + aB[3] + aC[3];

            if (mh == 1) {
                *(float4*)(cRed + (p*2 + dh)*512 + lane*16) =
                    make_float4(c0, c1, c2, c3);
            }
            asm volatile("bar.sync %0, %1;" :: "r"(p + 1), "r"(128) : "memory");
            if (mh == 0) {
                float4 o = *(const float4*)(cRed + (p*2 + dh)*512 + lane*16);
                c0 += o.x; c1 += o.y; c2 += o.z; c3 += o.w;
                int t2o = (lane & 3) * 2;
                float* o0 = outp + ((size_t)(b0 + gr) * 512 + ug) * 16 + dh*8;
                float* o1 = outp + ((size_t)(b0 + gr + 8) * 512 + ug) * 16 + dh*8;
                *(float2*)(o0 + t2o) = make_float2(c0, c1);
                *(float2*)(o1 + t2o) = make_float2(c2, c3);
            }
        }

        // ---- stage 4: store prefetched attn tile into alternate buffer ----
        if (more) {
            int b = lane >> 1, hf = lane & 1;
            char* pa = smc + 67584 + ((it + 1) & 1) * 5120 + p*1280 + b*80 + hf*16;
            *(uint4*)pa = nvh;
            *(uint4*)(pa + 32) = nvl;
        }
        __syncthreads();   // protect sS/sRed/sA before next iteration
    }
}

// ---------------------------------------------------------------------------
extern "C" void kernel_launch(void* const* d_in, const int* in_sizes, int n_in,
                              void* d_out, int out_size)
{
    const float* x    = (const float*)d_in[0];
    const float* W1   = (const float*)d_in[1];
    const float* b1   = (const float*)d_in[2];
    const float* W2   = (const float*)d_in[3];
    const float* b2   = (const float*)d_in[4];
    const float* temp = (const float*)d_in[5];
    const float* Ma   = (const float*)d_in[6];
    const float* Mv   = (const float*)d_in[7];

    float* attn = (float*)d_out;
    float* wout = attn + (size_t)B_ * U_ * D_;
    float* outp = wout + (size_t)B_ * B_ * U_;

    cudaFuncSetAttribute(hgemm2_k, cudaFuncAttributeMaxDynamicSharedMemorySize, 92160);
    cudaFuncSetAttribute(fused_attn, cudaFuncAttributeMaxDynamicSharedMemorySize, 230400);

    dim3 gW2(256, 32, 1);
    dim3 gMV(512, 4, 1);
    dim3 gG1(32, 4, 4);
    dim3 gG2(128, 2, 1);

    w2conv_k<<<gW2, 256>>>(W2);
    mvconv_k<<<gMV, 256>>>(Ma, Mv);
    gemm1_partial<<<gG1, 128>>>(x, W1);
    reduce_bias_h<<<256, 256>>>(b1);
    hgemm2_k<<<gG2, 256, 92160>>>(b2, attn);
    fused_attn<<<128, 512, 230400>>>(temp, wout, outp);
}

// round 16
// speedup vs baseline: 1.0353x; 1.0353x over previous
#include <cuda_runtime.h>
#include <cuda_bf16.h>
#include <cmath>

#define B_   256
#define U_   512
#define D_   16
#define M_   256

// device globals (allocation-free rule)
__device__ float g_hp[4][B_ * 1024];
__device__ __nv_bfloat16 g_hh[B_ * 1024];
__device__ __nv_bfloat16 g_hl[B_ * 1024];
__device__ __nv_bfloat16 g_w2h[8192 * 1024];
__device__ __nv_bfloat16 g_w2l[8192 * 1024];
__device__ __nv_bfloat16 g_ah[B_ * 8192];
__device__ __nv_bfloat16 g_al[B_ * 8192];
__device__ __nv_bfloat16 g_mah[U_ * M_ * D_];
__device__ __nv_bfloat16 g_mal[U_ * M_ * D_];
__device__ __nv_bfloat16 g_mvth[U_ * D_ * M_];
__device__ __nv_bfloat16 g_mvtl[U_ * D_ * M_];

typedef unsigned long long ull;
union F4U { float4 f; ull p[2]; float s[4]; };

__device__ __forceinline__ ull pk2(float a, float b) {
    ull r; asm("mov.b64 %0, {%1, %2};" : "=l"(r) : "f"(a), "f"(b)); return r;
}
__device__ __forceinline__ void upk2(ull v, float& a, float& b) {
    asm("mov.b64 {%0, %1}, %2;" : "=f"(a), "=f"(b) : "l"(v));
}
__device__ __forceinline__ void ffma2(ull& d, ull a, ull b) {
    asm("fma.rn.f32x2 %0, %1, %2, %0;" : "+l"(d) : "l"(a), "l"(b));
}
__device__ __forceinline__ void ldsm4(unsigned* r, unsigned addr) {
    asm volatile("ldmatrix.sync.aligned.m8n8.x4.shared.b16 {%0,%1,%2,%3}, [%4];"
        : "=r"(r[0]), "=r"(r[1]), "=r"(r[2]), "=r"(r[3]) : "r"(addr));
}
__device__ __forceinline__ void ldsm2(unsigned* r, unsigned addr) {
    asm volatile("ldmatrix.sync.aligned.m8n8.x2.shared.b16 {%0,%1}, [%2];"
        : "=r"(r[0]), "=r"(r[1]) : "r"(addr));
}
__device__ __forceinline__ void mma16816(float* d, const unsigned* a, const unsigned* b) {
    asm volatile(
        "mma.sync.aligned.m16n8k16.row.col.f32.bf16.bf16.f32 "
        "{%0,%1,%2,%3}, {%4,%5,%6,%7}, {%8,%9}, {%0,%1,%2,%3};"
        : "+f"(d[0]), "+f"(d[1]), "+f"(d[2]), "+f"(d[3])
        : "r"(a[0]), "r"(a[1]), "r"(a[2]), "r"(a[3]), "r"(b[0]), "r"(b[1]));
}
__device__ __forceinline__ unsigned pkbf2(float a, float b) {
    __nv_bfloat162 t = __floats2bfloat162_rn(a, b);
    return *(unsigned*)&t;
}
__device__ __forceinline__ void cpa16(unsigned dst, const void* src) {
    asm volatile("cp.async.cg.shared.global [%0], [%1], 16;" :: "r"(dst), "l"(src));
}

// ---------------------------------------------------------------------------
// GEMM1 partials (unchanged, passing)
// ---------------------------------------------------------------------------
__global__ void __launch_bounds__(128) gemm1_partial(
        const float* __restrict__ A, const float* __restrict__ Bm)
{
    __shared__ float As[16][68];
    __shared__ float Bs[16][32];

    const int tid = threadIdx.x;
    const int bx = blockIdx.x, by = blockIdx.y, bz = blockIdx.z;
    const int kBegin = bz * 256;
    const int tx = tid & 7;
    const int ty = tid >> 3;

    ull acc2[2][4];
    acc2[0][0]=0ull; acc2[0][1]=0ull; acc2[0][2]=0ull; acc2[0][3]=0ull;
    acc2[1][0]=0ull; acc2[1][1]=0ull; acc2[1][2]=0ull; acc2[1][3]=0ull;

    const float* Ablk = A + (size_t)by * 64 * 1024;
    const float* Bblk = Bm + bx * 32;

    const int ar = tid >> 2;
    const int akq = tid & 3;
    const int bkr = tid >> 3;
    const int bnq = tid & 7;

    {
        float4 v0 = *(const float4*)(Ablk + (size_t)ar * 1024 + kBegin + akq * 4);
        As[akq*4+0][ar] = v0.x; As[akq*4+1][ar] = v0.y;
        As[akq*4+2][ar] = v0.z; As[akq*4+3][ar] = v0.w;
        float4 v1 = *(const float4*)(Ablk + (size_t)(ar+32) * 1024 + kBegin + akq * 4);
        As[akq*4+0][ar+32] = v1.x; As[akq*4+1][ar+32] = v1.y;
        As[akq*4+2][ar+32] = v1.z; As[akq*4+3][ar+32] = v1.w;
        float4 vb = *(const float4*)(Bblk + (size_t)(kBegin + bkr) * 1024 + bnq * 4);
        *(float4*)(&Bs[bkr][bnq*4]) = vb;
    }
    __syncthreads();

    for (int k0 = kBegin; k0 < kBegin + 256; k0 += 16) {
        const bool more = (k0 + 16) < (kBegin + 256);
        float4 nA0, nA1, nB0;
        if (more) {
            nA0 = *(const float4*)(Ablk + (size_t)ar * 1024 + k0 + 16 + akq * 4);
            nA1 = *(const float4*)(Ablk + (size_t)(ar+32) * 1024 + k0 + 16 + akq * 4);
            nB0 = *(const float4*)(Bblk + (size_t)(k0 + 16 + bkr) * 1024 + bnq * 4);
        }
#pragma unroll
        for (int k = 0; k < 16; k++) {
            F4U ta; ta.f = *(const float4*)(&As[k][ty*4]);
            float4 vb = *(const float4*)(&Bs[k][tx*4]);
            ull bd0 = pk2(vb.x, vb.x);
            ull bd1 = pk2(vb.y, vb.y);
            ull bd2 = pk2(vb.z, vb.z);
            ull bd3 = pk2(vb.w, vb.w);
            ffma2(acc2[0][0], ta.p[0], bd0);
            ffma2(acc2[0][1], ta.p[0], bd1);
            ffma2(acc2[0][2], ta.p[0], bd2);
            ffma2(acc2[0][3], ta.p[0], bd3);
            ffma2(acc2[1][0], ta.p[1], bd0);
            ffma2(acc2[1][1], ta.p[1], bd1);
            ffma2(acc2[1][2], ta.p[1], bd2);
            ffma2(acc2[1][3], ta.p[1], bd3);
        }
        if (more) {
            __syncthreads();
            As[akq*4+0][ar] = nA0.x; As[akq*4+1][ar] = nA0.y;
            As[akq*4+2][ar] = nA0.z; As[akq*4+3][ar] = nA0.w;
            As[akq*4+0][ar+32] = nA1.x; As[akq*4+1][ar+32] = nA1.y;
            As[akq*4+2][ar+32] = nA1.z; As[akq*4+3][ar+32] = nA1.w;
            *(float4*)(&Bs[bkr][bnq*4]) = nB0;
            __syncthreads();
        }
    }

    float* Cs = &g_hp[bz][0];
#pragma unroll
    for (int r2 = 0; r2 < 2; r2++) {
        float s0[4], s1[4];
        upk2(acc2[r2][0], s0[0], s1[0]);
        upk2(acc2[r2][1], s0[1], s1[1]);
        upk2(acc2[r2][2], s0[2], s1[2]);
        upk2(acc2[r2][3], s0[3], s1[3]);
        int row0 = by*64 + ty*4 + 2*r2;
        int col = bx*32 + tx*4;
        *(float4*)(Cs + (size_t)row0 * 1024 + col) =
            make_float4(s0[0], s0[1], s0[2], s0[3]);
        *(float4*)(Cs + (size_t)(row0 + 1) * 1024 + col) =
            make_float4(s1[0], s1[1], s1[2], s1[3]);
    }
}

// ---------------------------------------------------------------------------
__global__ void __launch_bounds__(256) reduce_bias_h(const float* __restrict__ bias)
{
    int i = blockIdx.x * 256 + threadIdx.x;
    int col4 = i & 255;
    float4 a = *(const float4*)(&g_hp[0][i*4]);
    float4 b = *(const float4*)(&g_hp[1][i*4]);
    float4 c = *(const float4*)(&g_hp[2][i*4]);
    float4 d = *(const float4*)(&g_hp[3][i*4]);
    float4 bb = *(const float4*)(bias + col4*4);
    float v0 = a.x + b.x + c.x + d.x + bb.x;
    float v1 = a.y + b.y + c.y + d.y + bb.y;
    float v2 = a.z + b.z + c.z + d.z + bb.z;
    float v3 = a.w + b.w + c.w + d.w + bb.w;

    unsigned h01 = pkbf2(v0, v1);
    unsigned h23 = pkbf2(v2, v3);
    __nv_bfloat162 hh01 = *(__nv_bfloat162*)&h01;
    __nv_bfloat162 hh23 = *(__nv_bfloat162*)&h23;
    unsigned l01 = pkbf2(v0 - __low2float(hh01), v1 - __high2float(hh01));
    unsigned l23 = pkbf2(v2 - __low2float(hh23), v3 - __high2float(hh23));
    *(uint2*)(&g_hh[i*4]) = make_uint2(h01, h23);
    *(uint2*)(&g_hl[i*4]) = make_uint2(l01, l23);
}

// ---------------------------------------------------------------------------
__global__ void __launch_bounds__(256) w2conv_k(const float* __restrict__ W2)
{
    __shared__ float t[32][33];
    const int n0 = blockIdx.x * 32;
    const int k0 = blockIdx.y * 32;
    const int tid = threadIdx.x;
#pragma unroll
    for (int i = 0; i < 4; i++) {
        int idx = tid + i * 256;
        int kr = idx >> 5;
        int nc = idx & 31;
        t[kr][nc] = W2[(size_t)(k0 + kr) * 8192 + n0 + nc];
    }
    __syncthreads();
    int n = tid >> 3;
    int kc = tid & 7;
    float v0 = t[kc*4+0][n], v1 = t[kc*4+1][n], v2 = t[kc*4+2][n], v3 = t[kc*4+3][n];
    unsigned h01 = pkbf2(v0, v1);
    unsigned h23 = pkbf2(v2, v3);
    __nv_bfloat162 hh01 = *(__nv_bfloat162*)&h01;
    __nv_bfloat162 hh23 = *(__nv_bfloat162*)&h23;
    unsigned l01 = pkbf2(v0 - __low2float(hh01), v1 - __high2float(hh01));
    unsigned l23 = pkbf2(v2 - __low2float(hh23), v3 - __high2float(hh23));
    size_t o = (size_t)(n0 + n) * 1024 + k0 + kc*4;
    *(uint2*)(&g_w2h[o]) = make_uint2(h01, h23);
    *(uint2*)(&g_w2l[o]) = make_uint2(l01, l23);
}

// ---------------------------------------------------------------------------
__global__ void __launch_bounds__(256) mvconv_k(
        const float* __restrict__ Ma, const float* __restrict__ Mv)
{
    __shared__ float tv[16][68];
    const int u  = blockIdx.x;
    const int m0 = blockIdx.y * 64;
    const int t  = threadIdx.x;
    const int ml = t >> 2;
    const int q  = t & 3;

    {
        float4 v = *(const float4*)(Ma + ((size_t)(m0+ml)*512 + u)*16 + q*4);
        unsigned h01 = pkbf2(v.x, v.y);
        unsigned h23 = pkbf2(v.z, v.w);
        __nv_bfloat162 hh01 = *(__nv_bfloat162*)&h01;
        __nv_bfloat162 hh23 = *(__nv_bfloat162*)&h23;
        unsigned l01 = pkbf2(v.x - __low2float(hh01), v.y - __high2float(hh01));
        unsigned l23 = pkbf2(v.z - __low2float(hh23), v.w - __high2float(hh23));
        size_t o = ((size_t)u*256 + m0 + ml)*16 + q*4;
        *(uint2*)(&g_mah[o]) = make_uint2(h01, h23);
        *(uint2*)(&g_mal[o]) = make_uint2(l01, l23);
    }
    {
        float4 v = *(const float4*)(Mv + ((size_t)(m0+ml)*512 + u)*16 + q*4);
        tv[q*4+0][ml] = v.x;
        tv[q*4+1][ml] = v.y;
        tv[q*4+2][ml] = v.z;
        tv[q*4+3][ml] = v.w;
    }
    __syncthreads();
    {
        int d = t >> 4;
        int mq = t & 15;
        float v0 = tv[d][mq*4+0], v1 = tv[d][mq*4+1];
        float v2 = tv[d][mq*4+2], v3 = tv[d][mq*4+3];
        unsigned h01 = pkbf2(v0, v1);
        unsigned h23 = pkbf2(v2, v3);
        __nv_bfloat162 hh01 = *(__nv_bfloat162*)&h01;
        __nv_bfloat162 hh23 = *(__nv_bfloat162*)&h23;
        unsigned l01 = pkbf2(v0 - __low2float(hh01), v1 - __high2float(hh01));
        unsigned l23 = pkbf2(v2 - __low2float(hh23), v3 - __high2float(hh23));
        size_t o = ((size_t)u*16 + d)*256 + m0 + mq*4;
        *(uint2*)(&g_mvth[o]) = make_uint2(h01, h23);
        *(uint2*)(&g_mvtl[o]) = make_uint2(l01, l23);
    }
}

// ---------------------------------------------------------------------------
// GEMM2 v3: BN=128, 3-stage cp.async, ldsm4-merged B. grid (64, 2).
// Per 40960B stage: A_H 0, A_L 10240, B_H 20480, B_L 30720.
// ---------------------------------------------------------------------------
__global__ void __launch_bounds__(256) hgemm2_k(
        const float* __restrict__ bias, float* __restrict__ C)
{
    extern __shared__ __align__(16) char hsm[];
    const unsigned sbase = (unsigned)__cvta_generic_to_shared(hsm);
    const int tid = threadIdx.x;
    const int lane = tid & 31;
    const int wid = tid >> 5;
    const int wm = wid & 3;
    const int wn = wid >> 2;
    const int n0 = blockIdx.x * 128;
    const int m0 = blockIdx.y * 128;

    const int r0  = tid >> 2;          // 0..63
    const int kq  = tid & 3;
    const unsigned dA0 = (unsigned)(r0*40 + kq*8) * 2u;
    const unsigned dA1 = (unsigned)((r0+64)*40 + kq*8) * 2u;

    unsigned aOffH[2];
#pragma unroll
    for (int ti = 0; ti < 2; ti++) {
        int row = wm*32 + ti*16 + (lane & 15);
        int kb  = (lane >> 4) * 8;
        aOffH[ti] = (unsigned)(row*40 + kb) * 2u;
    }
    unsigned bOff4[4];
#pragma unroll
    for (int tjp = 0; tjp < 4; tjp++) {
        int row = wn*64 + tjp*16 + (lane & 7) + ((lane >> 4) & 1) * 8;
        int kb  = ((lane >> 3) & 1) * 8;
        bOff4[tjp] = 20480u + (unsigned)(row*40 + kb) * 2u;
    }

    float acc[2][8][4];
#pragma unroll
    for (int ti = 0; ti < 2; ti++)
#pragma unroll
        for (int tj = 0; tj < 8; tj++) {
            acc[ti][tj][0] = 0.f; acc[ti][tj][1] = 0.f;
            acc[ti][tj][2] = 0.f; acc[ti][tj][3] = 0.f;
        }

    const size_t sa0 = (size_t)(m0 + r0) * 1024 + kq*8;
    const size_t sa1 = (size_t)(m0 + r0 + 64) * 1024 + kq*8;
    const size_t sb0 = (size_t)(n0 + r0) * 1024 + kq*8;
    const size_t sb1 = (size_t)(n0 + r0 + 64) * 1024 + kq*8;

#pragma unroll
    for (int pf = 0; pf < 2; pf++) {
        unsigned buf = sbase + (unsigned)pf * 40960u;
        int kk = pf * 32;
        cpa16(buf + dA0,          &g_hh[sa0 + kk]);
        cpa16(buf + dA1,          &g_hh[sa1 + kk]);
        cpa16(buf + 10240u + dA0, &g_hl[sa0 + kk]);
        cpa16(buf + 10240u + dA1, &g_hl[sa1 + kk]);
        cpa16(buf + 20480u + dA0, &g_w2h[sb0 + kk]);
        cpa16(buf + 20480u + dA1, &g_w2h[sb1 + kk]);
        cpa16(buf + 30720u + dA0, &g_w2l[sb0 + kk]);
        cpa16(buf + 30720u + dA1, &g_w2l[sb1 + kk]);
        asm volatile("cp.async.commit_group;" ::: "memory");
    }

    for (int it = 0; it < 32; ++it) {
        if (it < 31)
            asm volatile("cp.async.wait_group 1;" ::: "memory");
        else
            asm volatile("cp.async.wait_group 0;" ::: "memory");
        __syncthreads();

        if (it + 2 < 32) {
            unsigned buf = sbase + (unsigned)((it + 2) % 3) * 40960u;
            int kk = (it + 2) * 32;
            cpa16(buf + dA0,          &g_hh[sa0 + kk]);
            cpa16(buf + dA1,          &g_hh[sa1 + kk]);
            cpa16(buf + 10240u + dA0, &g_hl[sa0 + kk]);
            cpa16(buf + 10240u + dA1, &g_hl[sa1 + kk]);
            cpa16(buf + 20480u + dA0, &g_w2h[sb0 + kk]);
            cpa16(buf + 20480u + dA1, &g_w2h[sb1 + kk]);
            cpa16(buf + 30720u + dA0, &g_w2l[sb0 + kk]);
            cpa16(buf + 30720u + dA1, &g_w2l[sb1 + kk]);
            asm volatile("cp.async.commit_group;" ::: "memory");
        }

        const unsigned base = sbase + (unsigned)(it % 3) * 40960u;
#pragma unroll
        for (int ks = 0; ks < 2; ks++) {
            const unsigned ko = (unsigned)ks * 32u;
            unsigned fah[2][4], fal[2][4], fbh[4][4], fbl[4][4];
#pragma unroll
            for (int ti = 0; ti < 2; ti++) {
                ldsm4(fah[ti], base + aOffH[ti] + ko);
                ldsm4(fal[ti], base + aOffH[ti] + 10240u + ko);
            }
#pragma unroll
            for (int tjp = 0; tjp < 4; tjp++) {
                ldsm4(fbh[tjp], base + bOff4[tjp] + ko);
                ldsm4(fbl[tjp], base + bOff4[tjp] + 10240u + ko);
            }
#pragma unroll
            for (int ti = 0; ti < 2; ti++)
#pragma unroll
                for (int tj = 0; tj < 8; tj++) {
                    const unsigned* bh = &fbh[tj >> 1][(tj & 1) * 2];
                    const unsigned* bl = &fbl[tj >> 1][(tj & 1) * 2];
                    mma16816(acc[ti][tj], fah[ti], bh);
                    mma16816(acc[ti][tj], fah[ti], bl);
                    mma16816(acc[ti][tj], fal[ti], bh);
                }
        }
    }

    const int gq = lane >> 2;
    const int t2 = (lane & 3) * 2;
#pragma unroll
    for (int ti = 0; ti < 2; ti++) {
        int row = m0 + wm*32 + ti*16 + gq;
#pragma unroll
        for (int tj = 0; tj < 8; tj++) {
            int col = n0 + wn*64 + tj*8 + t2;
            float2 bb = *(const float2*)(bias + col);
            float v0 = acc[ti][tj][0] + bb.x;
            float v1 = acc[ti][tj][1] + bb.y;
            float v2 = acc[ti][tj][2] + bb.x;
            float v3 = acc[ti][tj][3] + bb.y;
            *(float2*)(C + (size_t)row * 8192 + col) = make_float2(v0, v1);
            *(float2*)(C + (size_t)(row + 8) * 8192 + col) = make_float2(v2, v3);
            unsigned h01 = pkbf2(v0, v1);
            __nv_bfloat162 hh01 = *(__nv_bfloat162*)&h01;
            unsigned l01 = pkbf2(v0 - __low2float(hh01), v1 - __high2float(hh01));
            *(unsigned*)(&g_ah[(size_t)row*8192 + col]) = h01;
            *(unsigned*)(&g_al[(size_t)row*8192 + col]) = l01;
            unsigned h23 = pkbf2(v2, v3);
            __nv_bfloat162 hh23 = *(__nv_bfloat162*)&h23;
            unsigned l23 = pkbf2(v2 - __low2float(hh23), v3 - __high2float(hh23));
            *(unsigned*)(&g_ah[(size_t)(row+8)*8192 + col]) = h23;
            *(unsigned*)(&g_al[(size_t)(row+8)*8192 + col]) = l23;
        }
    }
}

// ---------------------------------------------------------------------------
// Fused v8 (round-13 build, 235.6us): PERSISTENT-U, 512 threads.
// smem bytes: sS   fp32 [4u*16b][264]     [0,      67584)
//             sA   [u][16b][80]           [67584,  72704)
//             sMa  [u][256m][80]          [72704,  154624)
//             sMvT [u][16d][1040]         [154624, 221184)
//             sRed [8 slots][512]         [221184, 225280)
// ---------------------------------------------------------------------------
__global__ void __launch_bounds__(512) fused_attn(
        const float* __restrict__ temp,
        float* __restrict__ wout,
        float* __restrict__ outp)
{
    extern __shared__ __align__(16) char smc[];
    float* sS = (float*)smc;
    const unsigned sbase = (unsigned)__cvta_generic_to_shared(smc);

    const int u0  = blockIdx.x * 4;
    const int tid = threadIdx.x;
    const int lane = tid & 31;
    const int wid  = tid >> 5;       // 0..15
    const int p    = wid >> 2;       // local u 0..3
    const int q    = wid & 3;        // quarter index
    const int ug   = u0 + p;

    const float tu = temp[ug];

    // ---- resident loads: Ma planes -> sMa, MvT planes -> sMvT ----
#pragma unroll
    for (int t = 0; t < 4; t++) {
        int idx = tid + t*512;            // 0..2047
        int ul = idx >> 9;
        int m  = (idx >> 1) & 255;
        int hf = idx & 1;
        size_t gi = (((size_t)(u0 + ul)*256 + m)*16) + hf*8;
        uint4 vh = *(const uint4*)(&g_mah[gi]);
        uint4 vl = *(const uint4*)(&g_mal[gi]);
        char* d = smc + 72704 + ul*20480 + m*80 + hf*16;
        *(uint4*)d = vh;
        *(uint4*)(d + 32) = vl;
    }
#pragma unroll
    for (int t = 0; t < 4; t++) {
        int idx = tid + t*512;
        int ul  = idx >> 9;
        int dd  = (idx >> 5) & 15;
        int seg = idx & 31;
        size_t gi = (((size_t)(u0 + ul)*16 + dd)*256) + seg*8;
        uint4 vh = *(const uint4*)(&g_mvth[gi]);
        uint4 vl = *(const uint4*)(&g_mvtl[gi]);
        char* pp = smc + 154624 + ul*16640 + dd*1040 + seg*16;
        *(uint4*)pp = vh;
        *(uint4*)(pp + 512) = vl;
    }
    __syncthreads();

    const unsigned sMa_u = sbase + 72704u  + (unsigned)p * 20480u;
    const unsigned sMv_u = sbase + 154624u + (unsigned)p * 16640u;
    const unsigned sA_u  = sbase + 67584u  + (unsigned)p * 1280u;
    char* cA_u = smc + 67584 + p * 1280;
    char* cRed = smc + 221184;

    for (int it = 0; it < 16; it++) {
        const int b0 = it * 16;

        // ---- stage 0: attn tile -> sA (all 4 u-warps write same data) ----
        {
            int b = lane >> 1, hf = lane & 1;
            size_t gi = (size_t)(b0 + b) * 8192 + (size_t)ug * 16 + hf * 8;
            uint4 vh = *(const uint4*)(&g_ah[gi]);
            uint4 vl = *(const uint4*)(&g_al[gi]);
            char* pa = cA_u + b*80 + hf*16;
            *(uint4*)pa = vh;
            *(uint4*)(pa + 32) = vl;
        }
        __syncwarp();
        unsigned fa_h[4], fa_l[4];
        {
            unsigned a = sA_u + (unsigned)((lane & 15) * 80 + (lane >> 4) * 16);
            ldsm4(fa_h, a);
            ldsm4(fa_l, a + 32u);
        }

        // ---- stage 1: scores; this warp: m in [q*64, q*64+64) ----
        {
            const int gq = lane >> 2, t2 = (lane & 3) * 2;
#pragma unroll 4
            for (int tj = 0; tj < 8; tj++) {
                int mbase = q*64 + tj*8;
                unsigned fb_h[2], fb_l[2];
                unsigned ba = sMa_u + (unsigned)((mbase + (lane & 7))*80 + ((lane >> 3) & 1)*16);
                ldsm2(fb_h, ba);
                ldsm2(fb_l, ba + 32u);
                float d4[4];
                d4[0] = 0.f; d4[1] = 0.f; d4[2] = 0.f; d4[3] = 0.f;
                mma16816(d4, fa_h, fb_h);
                mma16816(d4, fa_h, fb_l);
                mma16816(d4, fa_l, fb_h);
                int m = mbase + t2;
                float s0 = (m     == b0 + gq)     ? -INFINITY : d4[0] * tu;
                float s1 = (m + 1 == b0 + gq)     ? -INFINITY : d4[1] * tu;
                float s2 = (m     == b0 + gq + 8) ? -INFINITY : d4[2] * tu;
                float s3 = (m + 1 == b0 + gq + 8) ? -INFINITY : d4[3] * tu;
                *(float2*)(sS + (p*16 + gq)*264 + m)     = make_float2(s0, s1);
                *(float2*)(sS + (p*16 + gq + 8)*264 + m) = make_float2(s2, s3);
            }
        }
        asm volatile("bar.sync %0, %1;" :: "r"(p + 1), "r"(128) : "memory");

        // ---- stage 2: grouped softmax; one group per lane ----
        {
            int g = lane & 7;
            int b = q*4 + (lane >> 3);
            float* row = sS + (p*16 + b)*264 + g;
            float v[32];
            float mx = -INFINITY;
#pragma unroll
            for (int j = 0; j < 32; j++) { v[j] = row[j*8]; mx = fmaxf(mx, v[j]); }
            float s = 0.f;
#pragma unroll
            for (int j = 0; j < 32; j++) { v[j] = __expf(v[j] - mx); s += v[j]; }
            float inv = 1.f / (8.f * s);
#pragma unroll
            for (int j = 0; j < 32; j++) row[j*8] = v[j] * inv;
        }
        __syncthreads();

        // ---- stage 2b: weights store [b][m][u0..u0+3] (16B stores) ----
        {
            int b = tid >> 5;              // 0..15
#pragma unroll
            for (int mj = 0; mj < 8; mj++) {
                int m = lane + 32*mj;
                float4 w;
                w.x = sS[(0*16 + b)*264 + m];
                w.y = sS[(1*16 + b)*264 + m];
                w.z = sS[(2*16 + b)*264 + m];
                w.w = sS[(3*16 + b)*264 + m];
                *(float4*)(wout + ((size_t)(b0 + b)*256 + m)*512 + u0) = w;
            }
        }

        // ---- stage 3: outputs; warp = (d-half dh, mc-half mh) ----
        {
            const int dh = q & 1;
            const int mh = q >> 1;
            float aA[4], aB[4], aC[4];
            aA[0]=0.f; aA[1]=0.f; aA[2]=0.f; aA[3]=0.f;
            aB[0]=0.f; aB[1]=0.f; aB[2]=0.f; aB[3]=0.f;
            aC[0]=0.f; aC[1]=0.f; aC[2]=0.f; aC[3]=0.f;
            const int gr = lane >> 2;
            const int kc = (lane & 3) * 2;
#pragma unroll 4
            for (int mi = 0; mi < 8; mi++) {
                int mc = mh*8 + mi;
                const float* r0 = sS + (p*16 + gr)*264 + mc*16;
                const float* r1 = sS + (p*16 + gr + 8)*264 + mc*16;
                float2 v00 = *(const float2*)(r0 + kc);
                float2 v10 = *(const float2*)(r1 + kc);
                float2 v01 = *(const float2*)(r0 + kc + 8);
                float2 v11 = *(const float2*)(r1 + kc + 8);
                unsigned a_h[4], a_l[4];
                a_h[0] = pkbf2(v00.x, v00.y);
                a_h[1] = pkbf2(v10.x, v10.y);
                a_h[2] = pkbf2(v01.x, v01.y);
                a_h[3] = pkbf2(v11.x, v11.y);
                __nv_bfloat162 t0 = *(__nv_bfloat162*)&a_h[0];
                __nv_bfloat162 t1 = *(__nv_bfloat162*)&a_h[1];
                __nv_bfloat162 t2b = *(__nv_bfloat162*)&a_h[2];
                __nv_bfloat162 t3 = *(__nv_bfloat162*)&a_h[3];
                a_l[0] = pkbf2(v00.x - __low2float(t0), v00.y - __high2float(t0));
                a_l[1] = pkbf2(v10.x - __low2float(t1), v10.y - __high2float(t1));
                a_l[2] = pkbf2(v01.x - __low2float(t2b), v01.y - __high2float(t2b));
                a_l[3] = pkbf2(v11.x - __low2float(t3), v11.y - __high2float(t3));
                unsigned fb_h[2], fb_l[2];
                unsigned ba = sMv_u + (unsigned)((dh*8 + (lane & 7))*1040 + mc*32 + ((lane >> 3) & 1)*16);
                ldsm2(fb_h, ba);
                ldsm2(fb_l, ba + 512u);
                mma16816(aA, a_h, fb_h);
                mma16816(aB, a_h, fb_l);
                mma16816(aC, a_l, fb_h);
            }
            float c0 = aA[0] + aB[0] + aC[0];
            float c1 = aA[1] + aB[1] + aC[1];
            float c2 = aA[2] + aB[2] + aC[2];
            float c3 = aA[3] + aB[3] + aC[3];

            if (mh == 1) {
                *(float4*)(cRed + (p*2 + dh)*512 + lane*16) =
                    make_float4(c0, c1, c2, c3);
            }
            asm volatile("bar.sync %0, %1;" :: "r"(p + 1), "r"(128) : "memory");
            if (mh == 0) {
                float4 o = *(const float4*)(cRed + (p*2 + dh)*512 + lane*16);
                c0 += o.x; c1 += o.y; c2 += o.z; c3 += o.w;
                int t2o = (lane & 3) * 2;
                float* o0 = outp + ((size_t)(b0 + gr) * 512 + ug) * 16 + dh*8;
                float* o1 = outp + ((size_t)(b0 + gr + 8) * 512 + ug) * 16 + dh*8;
                *(float2*)(o0 + t2o) = make_float2(c0, c1);
                *(float2*)(o1 + t2o) = make_float2(c2, c3);
            }
        }
        __syncthreads();   // protect sS/sRed before next iteration
    }
}

// ---------------------------------------------------------------------------
extern "C" void kernel_launch(void* const* d_in, const int* in_sizes, int n_in,
                              void* d_out, int out_size)
{
    const float* x    = (const float*)d_in[0];
    const float* W1   = (const float*)d_in[1];
    const float* b1   = (const float*)d_in[2];
    const float* W2   = (const float*)d_in[3];
    const float* b2   = (const float*)d_in[4];
    const float* temp = (const float*)d_in[5];
    const float* Ma   = (const float*)d_in[6];
    const float* Mv   = (const float*)d_in[7];

    float* attn = (float*)d_out;
    float* wout = attn + (size_t)B_ * U_ * D_;
    float* outp = wout + (size_t)B_ * B_ * U_;

    cudaFuncSetAttribute(hgemm2_k, cudaFuncAttributeMaxDynamicSharedMemorySize, 122880);
    cudaFuncSetAttribute(fused_attn, cudaFuncAttributeMaxDynamicSharedMemorySize, 225280);

    dim3 gW2(256, 32, 1);
    dim3 gMV(512, 4, 1);
    dim3 gG1(32, 4, 4);
    dim3 gG2(64, 2, 1);

    // order chosen so ncu's captured slot (index 3) = hgemm2_k
    w2conv_k<<<gW2, 256>>>(W2);
    gemm1_partial<<<gG1, 128>>>(x, W1);
    reduce_bias_h<<<256, 256>>>(b1);
    hgemm2_k<<<gG2, 256, 122880>>>(b2, attn);
    mvconv_k<<<gMV, 256>>>(Ma, Mv);
    fused_attn<<<128, 512, 225280>>>(temp, wout, outp);
}